// round 14
// baseline (speedup 1.0000x reference)
#include <cuda_runtime.h>
#include <cuda_bf16.h>
#include <cuda_fp16.h>
#include <cstdint>
#include <cstddef>

// ---------------------------------------------------------------------------
// Problem constants
// ---------------------------------------------------------------------------
#define B_SZ   4
#define NH_    4
#define HD_    32
#define C_DIM  128
#define WS_    8
#define L_WIN  64
#define NWIN   1024
#define N_IMG  65536
#define TD_    100
#define T_TOT  65736
#define M_TOT  (B_SZ * T_TOT)   // 262944
#define SCALE_ 0.17677669529663687f

// Scratch (device globals) — q,k in fp16; v in bf16 hi/lo; ctx fp32
__device__ __half        g_q16[(size_t)M_TOT * 128];
__device__ __half        g_k16[(size_t)M_TOT * 128];
__device__ __nv_bfloat16 g_v_h[(size_t)M_TOT * 128];
__device__ __nv_bfloat16 g_v_l[(size_t)M_TOT * 128];
__device__ float g_ctx[(size_t)M_TOT * 128];
__device__ __nv_bfloat16 g_wq_h[384 * 128], g_wq_l[384 * 128];
__device__ __nv_bfloat16 g_wp_h[128 * 128], g_wp_l[128 * 128];
__device__ float g_bias[NH_ * L_WIN * L_WIN];

// ---------------------------------------------------------------------------
__device__ __forceinline__ const float* token_row(int r,
                                                  const float* __restrict__ x,
                                                  const float* __restrict__ det,
                                                  const float* __restrict__ inter)
{
    int b = r / T_TOT;
    int t = r - b * T_TOT;
    if (t < N_IMG)  return x     + ((size_t)b * N_IMG + t) * C_DIM;
    t -= N_IMG;
    if (t < TD_)    return det   + ((size_t)b * TD_   + t) * C_DIM;
    return inter + ((size_t)b * TD_ + (t - TD_)) * C_DIM;
}

// ---------------------------------------------------------------------------
// mma helpers (m16n8k16, fp32 accumulate)
// ---------------------------------------------------------------------------
__device__ __forceinline__ void mma_bf16(float c[4], const uint32_t a[4],
                                         uint32_t b0, uint32_t b1)
{
    asm volatile(
        "mma.sync.aligned.m16n8k16.row.col.f32.bf16.bf16.f32 "
        "{%0,%1,%2,%3}, {%4,%5,%6,%7}, {%8,%9}, {%0,%1,%2,%3};\n"
        : "+f"(c[0]), "+f"(c[1]), "+f"(c[2]), "+f"(c[3])
        : "r"(a[0]), "r"(a[1]), "r"(a[2]), "r"(a[3]), "r"(b0), "r"(b1));
}

__device__ __forceinline__ void mma_f16(float c[4], const uint32_t a[4],
                                        uint32_t b0, uint32_t b1)
{
    asm volatile(
        "mma.sync.aligned.m16n8k16.row.col.f32.f16.f16.f32 "
        "{%0,%1,%2,%3}, {%4,%5,%6,%7}, {%8,%9}, {%0,%1,%2,%3};\n"
        : "+f"(c[0]), "+f"(c[1]), "+f"(c[2]), "+f"(c[3])
        : "r"(a[0]), "r"(a[1]), "r"(a[2]), "r"(a[3]), "r"(b0), "r"(b1));
}

__device__ __forceinline__ void ldm_x4(uint32_t r[4], const void* p)
{
    uint32_t sa = (uint32_t)__cvta_generic_to_shared(p);
    asm volatile("ldmatrix.sync.aligned.m8n8.x4.shared.b16 {%0,%1,%2,%3}, [%4];"
                 : "=r"(r[0]), "=r"(r[1]), "=r"(r[2]), "=r"(r[3]) : "r"(sa));
}

__device__ __forceinline__ void ldm_x4_t(uint32_t r[4], const void* p)
{
    uint32_t sa = (uint32_t)__cvta_generic_to_shared(p);
    asm volatile("ldmatrix.sync.aligned.m8n8.x4.trans.shared.b16 {%0,%1,%2,%3}, [%4];"
                 : "=r"(r[0]), "=r"(r[1]), "=r"(r[2]), "=r"(r[3]) : "r"(sa));
}

__device__ __forceinline__ uint32_t pack_bf16x2(float e0, float e1)
{
    uint32_t r;
    asm("cvt.rn.bf16x2.f32 %0, %1, %2;" : "=r"(r) : "f"(e1), "f"(e0));
    return r;
}

// ---------------------------------------------------------------------------
// K0a: pregather rel-pos bias; K0b: split weights to bf16 hi/lo
// ---------------------------------------------------------------------------
__global__ void bias_gather_kernel(const float* __restrict__ rel_table,
                                   const int*   __restrict__ rel_index)
{
    int idx = blockIdx.x * 256 + threadIdx.x;
    if (idx < L_WIN * L_WIN) {
        int ri = rel_index[idx];
        #pragma unroll
        for (int h = 0; h < NH_; h++)
            g_bias[h * (L_WIN * L_WIN) + idx] = rel_table[ri * NH_ + h];
    }
}

__global__ void weight_split_kernel(const float* __restrict__ Wq,
                                    const float* __restrict__ Wp)
{
    int i = blockIdx.x * 256 + threadIdx.x;
    if (i < 384 * 128) {
        float v = Wq[i];
        __nv_bfloat16 h = __float2bfloat16(v);
        g_wq_h[i] = h;
        g_wq_l[i] = __float2bfloat16(v - __bfloat162float(h));
    }
    if (i < 128 * 128) {
        float v = Wp[i];
        __nv_bfloat16 h = __float2bfloat16(v);
        g_wp_h[i] = h;
        g_wp_l[i] = __float2bfloat16(v - __bfloat162float(h));
    }
}

// ---------------------------------------------------------------------------
// Tensor-core GEMM, bf16 hi/lo split (3 products).
// IS_QKV: epilogue routes columns to q(fp16) / k(fp16) / v(bf16 hi+lo).
// ---------------------------------------------------------------------------
template<bool IS_QKV>
__global__ __launch_bounds__(256, 2)
void mma_gemm_kernel(const float* __restrict__ x, const float* __restrict__ det,
                     const float* __restrict__ inter,
                     const float* __restrict__ bias, float* __restrict__ out_param)
{
    __shared__ __align__(16) __nv_bfloat16 Ah[128][40];
    __shared__ __align__(16) __nv_bfloat16 Al[128][40];
    __shared__ __align__(16) __nv_bfloat16 Bh[128][40];
    __shared__ __align__(16) __nv_bfloat16 Bl[128][40];

    const __nv_bfloat16* Wh = IS_QKV ? g_wq_h : g_wp_h;
    const __nv_bfloat16* Wl = IS_QKV ? g_wq_l : g_wp_l;

    const int m0   = blockIdx.y * 128;
    const int n0   = blockIdx.x * 128;
    const int tid  = threadIdx.x;
    const int lane = tid & 31;
    const int warp = tid >> 5;
    const int mbase = (warp >> 1) * 32;
    const int nbase = (warp & 1) * 64;

    float c[2][8][4] = {};
    float4 pa[4];
    uint4  pbh[2], pbl[2];

    // prologue: load chunk 0
    #pragma unroll
    for (int it = 0; it < 4; it++) {
        int idx = tid + it * 256;
        int row = idx >> 3;
        int c4  = (idx & 7) * 4;
        int r = m0 + row;
        pa[it] = make_float4(0.f, 0.f, 0.f, 0.f);
        if (r < M_TOT) {
            if (IS_QKV) pa[it] = *(const float4*)(token_row(r, x, det, inter) + c4);
            else        pa[it] = *(const float4*)(g_ctx + (size_t)r * 128 + c4);
        }
    }
    #pragma unroll
    for (int it = 0; it < 2; it++) {
        int idx = tid + it * 256;
        int row = idx >> 2, c8 = (idx & 3) * 8;
        pbh[it] = *(const uint4*)(Wh + (size_t)(n0 + row) * 128 + c8);
        pbl[it] = *(const uint4*)(Wl + (size_t)(n0 + row) * 128 + c8);
    }

    #pragma unroll
    for (int kc = 0; kc < 4; kc++) {
        #pragma unroll
        for (int it = 0; it < 4; it++) {
            int idx = tid + it * 256;
            int row = idx >> 3;
            int c4  = (idx & 7) * 4;
            float va[4] = {pa[it].x, pa[it].y, pa[it].z, pa[it].w};
            #pragma unroll
            for (int j = 0; j < 4; j++) {
                __nv_bfloat16 h = __float2bfloat16(va[j]);
                Ah[row][c4 + j] = h;
                Al[row][c4 + j] = __float2bfloat16(va[j] - __bfloat162float(h));
            }
        }
        #pragma unroll
        for (int it = 0; it < 2; it++) {
            int idx = tid + it * 256;
            int row = idx >> 2, c8 = (idx & 3) * 8;
            *(uint4*)&Bh[row][c8] = pbh[it];
            *(uint4*)&Bl[row][c8] = pbl[it];
        }
        __syncthreads();

        if (kc < 3) {
            int kk = (kc + 1) * 32;
            #pragma unroll
            for (int it = 0; it < 4; it++) {
                int idx = tid + it * 256;
                int row = idx >> 3;
                int c4  = (idx & 7) * 4;
                int r = m0 + row;
                pa[it] = make_float4(0.f, 0.f, 0.f, 0.f);
                if (r < M_TOT) {
                    if (IS_QKV) pa[it] = *(const float4*)(token_row(r, x, det, inter) + kk + c4);
                    else        pa[it] = *(const float4*)(g_ctx + (size_t)r * 128 + kk + c4);
                }
            }
            #pragma unroll
            for (int it = 0; it < 2; it++) {
                int idx = tid + it * 256;
                int row = idx >> 2, c8 = (idx & 3) * 8;
                pbh[it] = *(const uint4*)(Wh + (size_t)(n0 + row) * 128 + kk + c8);
                pbl[it] = *(const uint4*)(Wl + (size_t)(n0 + row) * 128 + kk + c8);
            }
        }

        #pragma unroll
        for (int kt = 0; kt < 32; kt += 16) {
            uint32_t ah[2][4], al[2][4];
            const int arow_in = lane & 15;
            const int acol = kt + ((lane >> 4) << 3);
            #pragma unroll
            for (int mi = 0; mi < 2; mi++) {
                ldm_x4(ah[mi], &Ah[mbase + mi * 16 + arow_in][acol]);
                ldm_x4(al[mi], &Al[mbase + mi * 16 + arow_in][acol]);
            }
            #pragma unroll
            for (int np = 0; np < 4; np++) {
                int mtx  = lane >> 3;
                int nrow = nbase + (np * 2 + (mtx >> 1)) * 8 + (lane & 7);
                int kcol = kt + (mtx & 1) * 8;
                uint32_t bh[4], bl[4];
                ldm_x4(bh, &Bh[nrow][kcol]);
                ldm_x4(bl, &Bl[nrow][kcol]);
                #pragma unroll
                for (int mi = 0; mi < 2; mi++)
                    #pragma unroll
                    for (int j = 0; j < 2; j++) {
                        mma_bf16(c[mi][np * 2 + j], ah[mi], bh[2 * j], bh[2 * j + 1]);
                        mma_bf16(c[mi][np * 2 + j], ah[mi], bl[2 * j], bl[2 * j + 1]);
                        mma_bf16(c[mi][np * 2 + j], al[mi], bh[2 * j], bh[2 * j + 1]);
                    }
            }
        }
        __syncthreads();
    }

    // ---- epilogue ----
    const int g = lane >> 2;
    const int t = lane & 3;
    // column block: 0=q, 1=k, 2=v (warp-uniform for IS_QKV)
    const int sblk = (n0 + nbase) >> 7;
    #pragma unroll
    for (int ni = 0; ni < 8; ni++) {
        int col = n0 + nbase + ni * 8 + t * 2;
        float2 bb = *(const float2*)(bias + col);
        int cc = col & 127;
        #pragma unroll
        for (int mi = 0; mi < 2; mi++) {
            #pragma unroll
            for (int rr = 0; rr < 2; rr++) {
                int r = m0 + mbase + mi * 16 + g + rr * 8;
                if (r < M_TOT) {
                    float v0 = c[mi][ni][rr * 2 + 0] + bb.x;
                    float v1 = c[mi][ni][rr * 2 + 1] + bb.y;
                    if (!IS_QKV) {
                        *(float2*)(out_param + (size_t)r * 128 + col) =
                            make_float2(v0, v1);
                    } else if (sblk == 0) {
                        *(__half2*)(g_q16 + (size_t)r * 128 + cc) =
                            __floats2half2_rn(v0, v1);
                    } else if (sblk == 1) {
                        *(__half2*)(g_k16 + (size_t)r * 128 + cc) =
                            __floats2half2_rn(v0, v1);
                    } else {
                        size_t off = (size_t)r * 128 + cc;
                        float h0 = __bfloat162float(__float2bfloat16(v0));
                        float h1 = __bfloat162float(__float2bfloat16(v1));
                        *(uint32_t*)(g_v_h + off) = pack_bf16x2(h0, h1);
                        *(uint32_t*)(g_v_l + off) = pack_bf16x2(v0 - h0, v1 - h1);
                    }
                }
            }
        }
    }
}

// ---------------------------------------------------------------------------
// K2: windowed attention.  Loads are straight uint4 copies (fp16 q/k,
// bf16 hi/lo v).  S: fp16 single; PV: bf16 hi/lo 3-term.
// ---------------------------------------------------------------------------
__global__ __launch_bounds__(128)
void win_attn_mma_kernel(const float* __restrict__ mask)
{
    const int h  = blockIdx.x;
    const int w  = blockIdx.y;
    const int b  = blockIdx.z;
    const int hy = w >> 5, wx = w & 31;
    const int tid  = threadIdx.x;
    const int lane = tid & 31;
    const int warp = tid >> 5;

    __shared__ __align__(16) __half      qs[64][40];
    __shared__ __align__(16) __half      ks[64][40];
    __shared__ __align__(16) __nv_bfloat16 vh[64][40], vl[64][40];

    // ---- load q,k,vh,vl: straight uint4 copies (8 halves each) ----
    #pragma unroll
    for (int it = 0; it < 8; it++) {
        int idx = tid + it * 128;            // 0..1023
        int mtx = idx >> 8;                  // 0=q 1=k 2=vh 3=vl
        int rem = idx & 255;
        int tok = rem >> 2;
        int c8  = (rem & 3) * 8;
        int wi = tok >> 3, wj = tok & 7;
        int t = (hy * 8 + wi) * 256 + (wx * 8 + wj);
        size_t base = ((size_t)(b * T_TOT + t)) * 128 + h * 32 + c8;
        uint4 val;
        void* dst;
        if (mtx == 0)      { val = *(const uint4*)(g_q16 + base); dst = &qs[tok][c8]; }
        else if (mtx == 1) { val = *(const uint4*)(g_k16 + base); dst = &ks[tok][c8]; }
        else if (mtx == 2) { val = *(const uint4*)(g_v_h + base); dst = &vh[tok][c8]; }
        else               { val = *(const uint4*)(g_v_l + base); dst = &vl[tok][c8]; }
        *(uint4*)dst = val;
    }
    __syncthreads();

    // ---- S = Q K^T (fp16, single product) ----
    const int mrow = warp * 16;
    float sc[8][4] = {};
    #pragma unroll
    for (int kt = 0; kt < 32; kt += 16) {
        uint32_t aq[4];
        const int arow = mrow + (lane & 15);
        const int acol = kt + ((lane >> 4) << 3);
        ldm_x4(aq, &qs[arow][acol]);
        #pragma unroll
        for (int np = 0; np < 4; np++) {
            int mtx  = lane >> 3;
            int nrow = (np * 2 + (mtx >> 1)) * 8 + (lane & 7);
            int kcol = kt + (mtx & 1) * 8;
            uint32_t bq[4];
            ldm_x4(bq, &ks[nrow][kcol]);
            #pragma unroll
            for (int j = 0; j < 2; j++)
                mma_f16(sc[np * 2 + j], aq, bq[2 * j], bq[2 * j + 1]);
        }
    }

    // ---- softmax in accumulator layout ----
    const int g = lane >> 2;
    const int t = lane & 3;
    const int r0 = mrow + g;
    const float* gbr0 = g_bias + h * (L_WIN * L_WIN) + r0 * 64;
    const float* mkr0 = mask + (size_t)w * (L_WIN * L_WIN) + r0 * 64;
    float mx0 = -1e30f, mx1 = -1e30f;
    #pragma unroll
    for (int j = 0; j < 8; j++) {
        int cbase = j * 8 + t * 2;
        float2 b0 = *(const float2*)(gbr0 + cbase);
        float2 m0 = *(const float2*)(mkr0 + cbase);
        float2 b1 = *(const float2*)(gbr0 + 8 * 64 + cbase);
        float2 m1 = *(const float2*)(mkr0 + 8 * 64 + cbase);
        sc[j][0] = sc[j][0] * SCALE_ + b0.x + m0.x;
        sc[j][1] = sc[j][1] * SCALE_ + b0.y + m0.y;
        sc[j][2] = sc[j][2] * SCALE_ + b1.x + m1.x;
        sc[j][3] = sc[j][3] * SCALE_ + b1.y + m1.y;
        mx0 = fmaxf(mx0, fmaxf(sc[j][0], sc[j][1]));
        mx1 = fmaxf(mx1, fmaxf(sc[j][2], sc[j][3]));
    }
    mx0 = fmaxf(mx0, __shfl_xor_sync(0xffffffffu, mx0, 1));
    mx0 = fmaxf(mx0, __shfl_xor_sync(0xffffffffu, mx0, 2));
    mx1 = fmaxf(mx1, __shfl_xor_sync(0xffffffffu, mx1, 1));
    mx1 = fmaxf(mx1, __shfl_xor_sync(0xffffffffu, mx1, 2));
    float sum0 = 0.f, sum1 = 0.f;
    #pragma unroll
    for (int j = 0; j < 8; j++) {
        sc[j][0] = __expf(sc[j][0] - mx0); sum0 += sc[j][0];
        sc[j][1] = __expf(sc[j][1] - mx0); sum0 += sc[j][1];
        sc[j][2] = __expf(sc[j][2] - mx1); sum1 += sc[j][2];
        sc[j][3] = __expf(sc[j][3] - mx1); sum1 += sc[j][3];
    }
    sum0 += __shfl_xor_sync(0xffffffffu, sum0, 1);
    sum0 += __shfl_xor_sync(0xffffffffu, sum0, 2);
    sum1 += __shfl_xor_sync(0xffffffffu, sum1, 1);
    sum1 += __shfl_xor_sync(0xffffffffu, sum1, 2);
    const float inv0 = 1.0f / sum0, inv1 = 1.0f / sum1;
    #pragma unroll
    for (int j = 0; j < 8; j++) {
        sc[j][0] *= inv0; sc[j][1] *= inv0;
        sc[j][2] *= inv1; sc[j][3] *= inv1;
    }

    // ---- repack P -> A-fragments (bf16 hi/lo) ----
    uint32_t pah[4][4], pal[4][4];
    #pragma unroll
    for (int kt2 = 0; kt2 < 4; kt2++) {
        #pragma unroll
        for (int half = 0; half < 2; half++) {
            const float* cc = sc[2 * kt2 + half];
            float h0 = __bfloat162float(__float2bfloat16(cc[0]));
            float h1 = __bfloat162float(__float2bfloat16(cc[1]));
            float h2 = __bfloat162float(__float2bfloat16(cc[2]));
            float h3 = __bfloat162float(__float2bfloat16(cc[3]));
            pah[kt2][half * 2 + 0] = pack_bf16x2(h0, h1);
            pah[kt2][half * 2 + 1] = pack_bf16x2(h2, h3);
            pal[kt2][half * 2 + 0] = pack_bf16x2(cc[0] - h0, cc[1] - h1);
            pal[kt2][half * 2 + 1] = pack_bf16x2(cc[2] - h2, cc[3] - h3);
        }
    }

    // ---- O = P V (bf16 hi/lo, 3-term) ----
    float oc[4][4] = {};
    #pragma unroll
    for (int kt2 = 0; kt2 < 4; kt2++) {
        int mtx = lane >> 3;
        int vrow = kt2 * 16 + (mtx & 1) * 8 + (lane & 7);
        uint32_t bh[2][4], bl[2][4];
        #pragma unroll
        for (int half = 0; half < 2; half++) {
            int vcol = half * 16 + (mtx >> 1) * 8;
            ldm_x4_t(bh[half], &vh[vrow][vcol]);
            ldm_x4_t(bl[half], &vl[vrow][vcol]);
        }
        #pragma unroll
        for (int half = 0; half < 2; half++)
            #pragma unroll
            for (int j = 0; j < 2; j++) {
                mma_bf16(oc[half * 2 + j], pah[kt2], bh[half][2 * j], bh[half][2 * j + 1]);
                mma_bf16(oc[half * 2 + j], pah[kt2], bl[half][2 * j], bl[half][2 * j + 1]);
                mma_bf16(oc[half * 2 + j], pal[kt2], bh[half][2 * j], bh[half][2 * j + 1]);
            }
    }

    // ---- store O ----
    #pragma unroll
    for (int rr = 0; rr < 2; rr++) {
        int l = r0 + rr * 8;
        int wi = l >> 3, wj = l & 7;
        int tk = (hy * 8 + wi) * 256 + (wx * 8 + wj);
        float* op = g_ctx + ((size_t)(b * T_TOT + tk)) * 128 + h * 32;
        #pragma unroll
        for (int ni = 0; ni < 4; ni++) {
            float2 v = rr ? make_float2(oc[ni][2], oc[ni][3])
                          : make_float2(oc[ni][0], oc[ni][1]);
            *(float2*)(op + ni * 8 + t * 2) = v;
        }
    }
}

// ---------------------------------------------------------------------------
// K3: det/inter token MHA.  Reads fp16 q/k and hi/lo v.
// ---------------------------------------------------------------------------
__global__ __launch_bounds__(128)
void tok_attn_kernel()
{
    const int h  = blockIdx.x;
    const int bt = blockIdx.y;
    const int qc = blockIdx.z;
    const int b  = bt >> 1, ty = bt & 1;
    const int tbase = N_IMG + ty * TD_;
    const int tid = threadIdx.x, lane = tid & 31, warp = tid >> 5;

    __shared__ __align__(16) float kt[32][104];
    __shared__ __align__(16) float vs[100][32];
    __shared__ float ps[4][104];

    for (int idx = tid; idx < 100 * 4; idx += 128) {
        int tok = idx >> 2;
        int c8  = (idx & 3) * 8;
        size_t base = ((size_t)(b * T_TOT + tbase + tok)) * 128 + h * 32 + c8;
        // k: fp16 -> fp32
        uint4 kv = *(const uint4*)(g_k16 + base);
        const __half2* kp = (const __half2*)&kv;
        // v: hi + lo bf16 -> fp32
        uint4 vhv = *(const uint4*)(g_v_h + base);
        uint4 vlv = *(const uint4*)(g_v_l + base);
        const __nv_bfloat162* hp = (const __nv_bfloat162*)&vhv;
        const __nv_bfloat162* lp = (const __nv_bfloat162*)&vlv;
        #pragma unroll
        for (int i = 0; i < 4; i++) {
            float2 kf = __half22float2(kp[i]);
            kt[c8 + 2 * i][tok]     = kf.x;
            kt[c8 + 2 * i + 1][tok] = kf.y;
            float2 hf = __bfloat1622float2(hp[i]);
            float2 lf = __bfloat1622float2(lp[i]);
            vs[tok][c8 + 2 * i]     = hf.x + lf.x;
            vs[tok][c8 + 2 * i + 1] = hf.y + lf.y;
        }
    }
    __syncthreads();

    const int q = qc * 4 + warp;
    float qv[32];
    {
        const __half* qp = g_q16 + ((size_t)(b * T_TOT + tbase + q)) * 128 + h * 32;
        #pragma unroll
        for (int d2 = 0; d2 < 16; d2++) {
            float2 f = __half22float2(*(const __half2*)(qp + d2 * 2));
            qv[d2 * 2]     = f.x * SCALE_;
            qv[d2 * 2 + 1] = f.y * SCALE_;
        }
    }
    float s[4];
    float mx = -1e30f;
    #pragma unroll
    for (int m = 0; m < 4; m++) {
        int j = lane + m * 32;
        float acc = -1e30f;
        if (j < 100) {
            acc = 0.f;
            #pragma unroll
            for (int d = 0; d < 32; d++) acc += qv[d] * kt[d][j];
        }
        s[m] = acc;
        mx = fmaxf(mx, acc);
    }
    #pragma unroll
    for (int o = 16; o > 0; o >>= 1)
        mx = fmaxf(mx, __shfl_xor_sync(0xffffffffu, mx, o));
    float sum = 0.f;
    #pragma unroll
    for (int m = 0; m < 4; m++) {
        int j = lane + m * 32;
        if (j < 100) { s[m] = __expf(s[m] - mx); sum += s[m]; }
        else s[m] = 0.f;
    }
    #pragma unroll
    for (int o = 16; o > 0; o >>= 1)
        sum += __shfl_xor_sync(0xffffffffu, sum, o);
    float inv = 1.0f / sum;
    #pragma unroll
    for (int m = 0; m < 4; m++) {
        int j = lane + m * 32;
        if (j < 100) ps[warp][j] = s[m] * inv;
    }
    __syncwarp();

    float o = 0.f;
    #pragma unroll 10
    for (int j = 0; j < 100; j++)
        o += ps[warp][j] * vs[j][lane];
    g_ctx[((size_t)(b * T_TOT + tbase + q)) * 128 + h * 32 + lane] = o;
}

// ---------------------------------------------------------------------------
// kernel_launch
// ---------------------------------------------------------------------------
extern "C" void kernel_launch(void* const* d_in, const int* in_sizes, int n_in,
                              void* d_out, int out_size)
{
    (void)in_sizes; (void)n_in; (void)out_size;
    const float* x        = (const float*)d_in[0];
    const float* det      = (const float*)d_in[1];
    const float* inter    = (const float*)d_in[2];
    const float* mask     = (const float*)d_in[3];
    const float* W_qkv    = (const float*)d_in[4];
    const float* b_qkv    = (const float*)d_in[5];
    const float* W_proj   = (const float*)d_in[6];
    const float* b_proj   = (const float*)d_in[7];
    const float* rel_tab  = (const float*)d_in[8];
    const int*   rel_idx  = (const int*)d_in[9];
    float* out = (float*)d_out;

    const int m_tiles = (M_TOT + 127) / 128;   // 2055

    bias_gather_kernel<<<16, 256>>>(rel_tab, rel_idx);
    weight_split_kernel<<<192, 256>>>(W_qkv, W_proj);
    mma_gemm_kernel<true><<<dim3(3, m_tiles), 256>>>(x, det, inter, b_qkv, nullptr);
    win_attn_mma_kernel<<<dim3(NH_, NWIN, B_SZ), 128>>>(mask);
    tok_attn_kernel<<<dim3(NH_, B_SZ * 2, 25), 128>>>();
    mma_gemm_kernel<false><<<dim3(1, m_tiles), 256>>>(nullptr, nullptr, nullptr,
                                                      b_proj, out);
}

// round 15
// speedup vs baseline: 1.0092x; 1.0092x over previous
#include <cuda_runtime.h>
#include <cuda_bf16.h>
#include <cuda_fp16.h>
#include <cstdint>
#include <cstddef>

// ---------------------------------------------------------------------------
// Problem constants
// ---------------------------------------------------------------------------
#define B_SZ   4
#define NH_    4
#define HD_    32
#define C_DIM  128
#define WS_    8
#define L_WIN  64
#define NWIN   1024
#define N_IMG  65536
#define TD_    100
#define T_TOT  65736
#define M_TOT  (B_SZ * T_TOT)   // 262944
#define SCALE_ 0.17677669529663687f

// Scratch (device globals) — q,k fp16; v,ctx bf16 hi/lo
__device__ __half        g_q16[(size_t)M_TOT * 128];
__device__ __half        g_k16[(size_t)M_TOT * 128];
__device__ __nv_bfloat16 g_v_h[(size_t)M_TOT * 128];
__device__ __nv_bfloat16 g_v_l[(size_t)M_TOT * 128];
__device__ __nv_bfloat16 g_ctx_h[(size_t)M_TOT * 128];
__device__ __nv_bfloat16 g_ctx_l[(size_t)M_TOT * 128];
__device__ __nv_bfloat16 g_wq_h[384 * 128], g_wq_l[384 * 128];
__device__ __nv_bfloat16 g_wp_h[128 * 128], g_wp_l[128 * 128];
__device__ float g_bias[NH_ * L_WIN * L_WIN];

// ---------------------------------------------------------------------------
__device__ __forceinline__ const float* token_row(int r,
                                                  const float* __restrict__ x,
                                                  const float* __restrict__ det,
                                                  const float* __restrict__ inter)
{
    int b = r / T_TOT;
    int t = r - b * T_TOT;
    if (t < N_IMG)  return x     + ((size_t)b * N_IMG + t) * C_DIM;
    t -= N_IMG;
    if (t < TD_)    return det   + ((size_t)b * TD_   + t) * C_DIM;
    return inter + ((size_t)b * TD_ + (t - TD_)) * C_DIM;
}

// ---------------------------------------------------------------------------
// mma helpers (m16n8k16, fp32 accumulate)
// ---------------------------------------------------------------------------
__device__ __forceinline__ void mma_bf16(float c[4], const uint32_t a[4],
                                         uint32_t b0, uint32_t b1)
{
    asm volatile(
        "mma.sync.aligned.m16n8k16.row.col.f32.bf16.bf16.f32 "
        "{%0,%1,%2,%3}, {%4,%5,%6,%7}, {%8,%9}, {%0,%1,%2,%3};\n"
        : "+f"(c[0]), "+f"(c[1]), "+f"(c[2]), "+f"(c[3])
        : "r"(a[0]), "r"(a[1]), "r"(a[2]), "r"(a[3]), "r"(b0), "r"(b1));
}

__device__ __forceinline__ void mma_f16(float c[4], const uint32_t a[4],
                                        uint32_t b0, uint32_t b1)
{
    asm volatile(
        "mma.sync.aligned.m16n8k16.row.col.f32.f16.f16.f32 "
        "{%0,%1,%2,%3}, {%4,%5,%6,%7}, {%8,%9}, {%0,%1,%2,%3};\n"
        : "+f"(c[0]), "+f"(c[1]), "+f"(c[2]), "+f"(c[3])
        : "r"(a[0]), "r"(a[1]), "r"(a[2]), "r"(a[3]), "r"(b0), "r"(b1));
}

__device__ __forceinline__ void ldm_x4(uint32_t r[4], const void* p)
{
    uint32_t sa = (uint32_t)__cvta_generic_to_shared(p);
    asm volatile("ldmatrix.sync.aligned.m8n8.x4.shared.b16 {%0,%1,%2,%3}, [%4];"
                 : "=r"(r[0]), "=r"(r[1]), "=r"(r[2]), "=r"(r[3]) : "r"(sa));
}

__device__ __forceinline__ void ldm_x4_t(uint32_t r[4], const void* p)
{
    uint32_t sa = (uint32_t)__cvta_generic_to_shared(p);
    asm volatile("ldmatrix.sync.aligned.m8n8.x4.trans.shared.b16 {%0,%1,%2,%3}, [%4];"
                 : "=r"(r[0]), "=r"(r[1]), "=r"(r[2]), "=r"(r[3]) : "r"(sa));
}

__device__ __forceinline__ uint32_t pack_bf16x2(float e0, float e1)
{
    uint32_t r;
    asm("cvt.rn.bf16x2.f32 %0, %1, %2;" : "=r"(r) : "f"(e1), "f"(e0));
    return r;
}

// ---------------------------------------------------------------------------
// K0a: pregather rel-pos bias; K0b: split weights to bf16 hi/lo
// ---------------------------------------------------------------------------
__global__ void bias_gather_kernel(const float* __restrict__ rel_table,
                                   const int*   __restrict__ rel_index)
{
    int idx = blockIdx.x * 256 + threadIdx.x;
    if (idx < L_WIN * L_WIN) {
        int ri = rel_index[idx];
        #pragma unroll
        for (int h = 0; h < NH_; h++)
            g_bias[h * (L_WIN * L_WIN) + idx] = rel_table[ri * NH_ + h];
    }
}

__global__ void weight_split_kernel(const float* __restrict__ Wq,
                                    const float* __restrict__ Wp)
{
    int i = blockIdx.x * 256 + threadIdx.x;
    if (i < 384 * 128) {
        float v = Wq[i];
        __nv_bfloat16 h = __float2bfloat16(v);
        g_wq_h[i] = h;
        g_wq_l[i] = __float2bfloat16(v - __bfloat162float(h));
    }
    if (i < 128 * 128) {
        float v = Wp[i];
        __nv_bfloat16 h = __float2bfloat16(v);
        g_wp_h[i] = h;
        g_wp_l[i] = __float2bfloat16(v - __bfloat162float(h));
    }
}

// ---------------------------------------------------------------------------
// Tensor-core GEMM, bf16 hi/lo split (3 products), double-buffered smem.
// IS_QKV:  A = tokens fp32 (converted in-flight), out -> q16/k16/v hi+lo.
// !IS_QKV: A = ctx bf16 hi/lo (pure uint4 copies),  out -> fp32 param.
// Dynamic smem: 2 stages x (Ah,Al,Bh,Bl)[128][40] bf16 = 81920 B.
// ---------------------------------------------------------------------------
template<bool IS_QKV>
__global__ __launch_bounds__(256, 2)
void mma_gemm_kernel(const float* __restrict__ x, const float* __restrict__ det,
                     const float* __restrict__ inter,
                     const float* __restrict__ bias, float* __restrict__ out_param)
{
    extern __shared__ __align__(16) __nv_bfloat16 sm[];
    // stage layout (elements): Ah 0, Al 5120, Bh 10240, Bl 15360; stage stride 20480

    const __nv_bfloat16* Wh = IS_QKV ? g_wq_h : g_wp_h;
    const __nv_bfloat16* Wl = IS_QKV ? g_wq_l : g_wp_l;

    const int m0   = blockIdx.y * 128;
    const int n0   = blockIdx.x * 128;
    const int tid  = threadIdx.x;
    const int lane = tid & 31;
    const int warp = tid >> 5;
    const int mbase = (warp >> 1) * 32;
    const int nbase = (warp & 1) * 64;

    float c[2][8][4] = {};
    float4 pa[4];                 // qkv A staging (fp32)
    uint4  pca_h[2], pca_l[2];    // proj A staging (bf16 hi/lo)
    uint4  pbh[2], pbl[2];

    auto loadA = [&](int kk) {
        if (IS_QKV) {
            #pragma unroll
            for (int it = 0; it < 4; it++) {
                int idx = tid + it * 256;
                int row = idx >> 3, c4 = (idx & 7) * 4;
                int r = m0 + row;
                pa[it] = make_float4(0.f, 0.f, 0.f, 0.f);
                if (r < M_TOT)
                    pa[it] = *(const float4*)(token_row(r, x, det, inter) + kk + c4);
            }
        } else {
            #pragma unroll
            for (int it = 0; it < 2; it++) {
                int idx = tid + it * 256;
                int row = idx >> 2, c8 = (idx & 3) * 8;
                int r = m0 + row;
                pca_h[it] = make_uint4(0, 0, 0, 0);
                pca_l[it] = make_uint4(0, 0, 0, 0);
                if (r < M_TOT) {
                    pca_h[it] = *(const uint4*)(g_ctx_h + (size_t)r * 128 + kk + c8);
                    pca_l[it] = *(const uint4*)(g_ctx_l + (size_t)r * 128 + kk + c8);
                }
            }
        }
    };
    auto loadB = [&](int kk) {
        #pragma unroll
        for (int it = 0; it < 2; it++) {
            int idx = tid + it * 256;
            int row = idx >> 2, c8 = (idx & 3) * 8;
            pbh[it] = *(const uint4*)(Wh + (size_t)(n0 + row) * 128 + kk + c8);
            pbl[it] = *(const uint4*)(Wl + (size_t)(n0 + row) * 128 + kk + c8);
        }
    };
    auto storeS = [&](int s) {
        __nv_bfloat16* Ah = sm + s * 20480;
        __nv_bfloat16* Al = Ah + 5120;
        __nv_bfloat16* Bh = Al + 5120;
        __nv_bfloat16* Bl = Bh + 5120;
        if (IS_QKV) {
            #pragma unroll
            for (int it = 0; it < 4; it++) {
                int idx = tid + it * 256;
                int row = idx >> 3, c4 = (idx & 7) * 4;
                float va[4] = {pa[it].x, pa[it].y, pa[it].z, pa[it].w};
                #pragma unroll
                for (int j = 0; j < 4; j++) {
                    __nv_bfloat16 h = __float2bfloat16(va[j]);
                    Ah[row * 40 + c4 + j] = h;
                    Al[row * 40 + c4 + j] = __float2bfloat16(va[j] - __bfloat162float(h));
                }
            }
        } else {
            #pragma unroll
            for (int it = 0; it < 2; it++) {
                int idx = tid + it * 256;
                int row = idx >> 2, c8 = (idx & 3) * 8;
                *(uint4*)(Ah + row * 40 + c8) = pca_h[it];
                *(uint4*)(Al + row * 40 + c8) = pca_l[it];
            }
        }
        #pragma unroll
        for (int it = 0; it < 2; it++) {
            int idx = tid + it * 256;
            int row = idx >> 2, c8 = (idx & 3) * 8;
            *(uint4*)(Bh + row * 40 + c8) = pbh[it];
            *(uint4*)(Bl + row * 40 + c8) = pbl[it];
        }
    };
    auto compute = [&](int s) {
        const __nv_bfloat16* Ah = sm + s * 20480;
        const __nv_bfloat16* Al = Ah + 5120;
        const __nv_bfloat16* Bh = Al + 5120;
        const __nv_bfloat16* Bl = Bh + 5120;
        #pragma unroll
        for (int kt = 0; kt < 32; kt += 16) {
            uint32_t ah[2][4], al[2][4];
            const int arow = mbase + (lane & 15);
            const int acol = kt + ((lane >> 4) << 3);
            #pragma unroll
            for (int mi = 0; mi < 2; mi++) {
                ldm_x4(ah[mi], Ah + (arow + mi * 16) * 40 + acol);
                ldm_x4(al[mi], Al + (arow + mi * 16) * 40 + acol);
            }
            #pragma unroll
            for (int np = 0; np < 4; np++) {
                int mtx  = lane >> 3;
                int nrow = nbase + (np * 2 + (mtx >> 1)) * 8 + (lane & 7);
                int kcol = kt + (mtx & 1) * 8;
                uint32_t bh[4], bl[4];
                ldm_x4(bh, Bh + nrow * 40 + kcol);
                ldm_x4(bl, Bl + nrow * 40 + kcol);
                #pragma unroll
                for (int mi = 0; mi < 2; mi++)
                    #pragma unroll
                    for (int j = 0; j < 2; j++) {
                        mma_bf16(c[mi][np * 2 + j], ah[mi], bh[2 * j], bh[2 * j + 1]);
                        mma_bf16(c[mi][np * 2 + j], ah[mi], bl[2 * j], bl[2 * j + 1]);
                        mma_bf16(c[mi][np * 2 + j], al[mi], bh[2 * j], bh[2 * j + 1]);
                    }
            }
        }
    };

    // ---- pipelined mainloop: 1 sync per chunk ----
    loadA(0);  loadB(0);
    storeS(0);
    loadA(32); loadB(32);
    __syncthreads();
    #pragma unroll
    for (int kc = 0; kc < 4; kc++) {
        int cur = kc & 1;
        if (kc < 3) storeS(cur ^ 1);
        if (kc < 2) { loadA((kc + 2) * 32); loadB((kc + 2) * 32); }
        compute(cur);
        __syncthreads();
    }

    // ---- epilogue: route q/k -> fp16, v -> bf16 hi/lo, proj -> fp32 ----
    const int g = lane >> 2;
    const int t = lane & 3;
    const int sblk = (n0 + nbase) >> 7;     // warp-uniform for IS_QKV
    #pragma unroll
    for (int ni = 0; ni < 8; ni++) {
        int col = n0 + nbase + ni * 8 + t * 2;
        float2 bb = *(const float2*)(bias + col);
        int cc = col & 127;
        #pragma unroll
        for (int mi = 0; mi < 2; mi++) {
            #pragma unroll
            for (int rr = 0; rr < 2; rr++) {
                int r = m0 + mbase + mi * 16 + g + rr * 8;
                if (r < M_TOT) {
                    float v0 = c[mi][ni][rr * 2 + 0] + bb.x;
                    float v1 = c[mi][ni][rr * 2 + 1] + bb.y;
                    if (!IS_QKV) {
                        *(float2*)(out_param + (size_t)r * 128 + col) =
                            make_float2(v0, v1);
                    } else if (sblk == 0) {
                        *(__half2*)(g_q16 + (size_t)r * 128 + cc) =
                            __floats2half2_rn(v0, v1);
                    } else if (sblk == 1) {
                        *(__half2*)(g_k16 + (size_t)r * 128 + cc) =
                            __floats2half2_rn(v0, v1);
                    } else {
                        size_t off = (size_t)r * 128 + cc;
                        float h0 = __bfloat162float(__float2bfloat16(v0));
                        float h1 = __bfloat162float(__float2bfloat16(v1));
                        *(uint32_t*)(g_v_h + off) = pack_bf16x2(h0, h1);
                        *(uint32_t*)(g_v_l + off) = pack_bf16x2(v0 - h0, v1 - h1);
                    }
                }
            }
        }
    }
}

// ---------------------------------------------------------------------------
// K2: windowed attention.  Pure uint4 loads; fp16 S; max-free softmax;
// bf16 hi/lo PV; O stored as bf16 hi/lo.
// ---------------------------------------------------------------------------
__global__ __launch_bounds__(128)
void win_attn_mma_kernel(const float* __restrict__ mask)
{
    const int h  = blockIdx.x;
    const int w  = blockIdx.y;
    const int b  = blockIdx.z;
    const int hy = w >> 5, wx = w & 31;
    const int tid  = threadIdx.x;
    const int lane = tid & 31;
    const int warp = tid >> 5;

    __shared__ __align__(16) __half        qs[64][40];
    __shared__ __align__(16) __half        ks[64][40];
    __shared__ __align__(16) __nv_bfloat16 vh[64][40], vl[64][40];

    // ---- load q,k,vh,vl: straight uint4 copies ----
    #pragma unroll
    for (int it = 0; it < 8; it++) {
        int idx = tid + it * 128;            // 0..1023
        int mtx = idx >> 8;                  // 0=q 1=k 2=vh 3=vl
        int rem = idx & 255;
        int tok = rem >> 2;
        int c8  = (rem & 3) * 8;
        int wi = tok >> 3, wj = tok & 7;
        int t = (hy * 8 + wi) * 256 + (wx * 8 + wj);
        size_t base = ((size_t)(b * T_TOT + t)) * 128 + h * 32 + c8;
        uint4 val;
        void* dst;
        if (mtx == 0)      { val = *(const uint4*)(g_q16 + base); dst = &qs[tok][c8]; }
        else if (mtx == 1) { val = *(const uint4*)(g_k16 + base); dst = &ks[tok][c8]; }
        else if (mtx == 2) { val = *(const uint4*)(g_v_h + base); dst = &vh[tok][c8]; }
        else               { val = *(const uint4*)(g_v_l + base); dst = &vl[tok][c8]; }
        *(uint4*)dst = val;
    }
    __syncthreads();

    // ---- S = Q K^T (fp16, single product) ----
    const int mrow = warp * 16;
    float sc[8][4] = {};
    #pragma unroll
    for (int kt = 0; kt < 32; kt += 16) {
        uint32_t aq[4];
        const int arow = mrow + (lane & 15);
        const int acol = kt + ((lane >> 4) << 3);
        ldm_x4(aq, &qs[arow][acol]);
        #pragma unroll
        for (int np = 0; np < 4; np++) {
            int mtx  = lane >> 3;
            int nrow = (np * 2 + (mtx >> 1)) * 8 + (lane & 7);
            int kcol = kt + (mtx & 1) * 8;
            uint32_t bq[4];
            ldm_x4(bq, &ks[nrow][kcol]);
            #pragma unroll
            for (int j = 0; j < 2; j++)
                mma_f16(sc[np * 2 + j], aq, bq[2 * j], bq[2 * j + 1]);
        }
    }

    // ---- max-free softmax in accumulator layout ----
    const int g = lane >> 2;
    const int t = lane & 3;
    const int r0 = mrow + g;
    const float* gbr0 = g_bias + h * (L_WIN * L_WIN) + r0 * 64;
    const float* mkr0 = mask + (size_t)w * (L_WIN * L_WIN) + r0 * 64;
    float sum0 = 0.f, sum1 = 0.f;
    #pragma unroll
    for (int j = 0; j < 8; j++) {
        int cbase = j * 8 + t * 2;
        float2 b0 = *(const float2*)(gbr0 + cbase);
        float2 m0 = *(const float2*)(mkr0 + cbase);
        float2 b1 = *(const float2*)(gbr0 + 8 * 64 + cbase);
        float2 m1 = *(const float2*)(mkr0 + 8 * 64 + cbase);
        sc[j][0] = __expf(sc[j][0] * SCALE_ + b0.x + m0.x); sum0 += sc[j][0];
        sc[j][1] = __expf(sc[j][1] * SCALE_ + b0.y + m0.y); sum0 += sc[j][1];
        sc[j][2] = __expf(sc[j][2] * SCALE_ + b1.x + m1.x); sum1 += sc[j][2];
        sc[j][3] = __expf(sc[j][3] * SCALE_ + b1.y + m1.y); sum1 += sc[j][3];
    }
    sum0 += __shfl_xor_sync(0xffffffffu, sum0, 1);
    sum0 += __shfl_xor_sync(0xffffffffu, sum0, 2);
    sum1 += __shfl_xor_sync(0xffffffffu, sum1, 1);
    sum1 += __shfl_xor_sync(0xffffffffu, sum1, 2);
    const float inv0 = 1.0f / sum0, inv1 = 1.0f / sum1;
    #pragma unroll
    for (int j = 0; j < 8; j++) {
        sc[j][0] *= inv0; sc[j][1] *= inv0;
        sc[j][2] *= inv1; sc[j][3] *= inv1;
    }

    // ---- repack P -> A-fragments (bf16 hi/lo) ----
    uint32_t pah[4][4], pal[4][4];
    #pragma unroll
    for (int kt2 = 0; kt2 < 4; kt2++) {
        #pragma unroll
        for (int half = 0; half < 2; half++) {
            const float* cc = sc[2 * kt2 + half];
            float h0 = __bfloat162float(__float2bfloat16(cc[0]));
            float h1 = __bfloat162float(__float2bfloat16(cc[1]));
            float h2 = __bfloat162float(__float2bfloat16(cc[2]));
            float h3 = __bfloat162float(__float2bfloat16(cc[3]));
            pah[kt2][half * 2 + 0] = pack_bf16x2(h0, h1);
            pah[kt2][half * 2 + 1] = pack_bf16x2(h2, h3);
            pal[kt2][half * 2 + 0] = pack_bf16x2(cc[0] - h0, cc[1] - h1);
            pal[kt2][half * 2 + 1] = pack_bf16x2(cc[2] - h2, cc[3] - h3);
        }
    }

    // ---- O = P V (bf16 hi/lo, 3-term) ----
    float oc[4][4] = {};
    #pragma unroll
    for (int kt2 = 0; kt2 < 4; kt2++) {
        int mtx = lane >> 3;
        int vrow = kt2 * 16 + (mtx & 1) * 8 + (lane & 7);
        uint32_t bh[2][4], bl[2][4];
        #pragma unroll
        for (int half = 0; half < 2; half++) {
            int vcol = half * 16 + (mtx >> 1) * 8;
            ldm_x4_t(bh[half], &vh[vrow][vcol]);
            ldm_x4_t(bl[half], &vl[vrow][vcol]);
        }
        #pragma unroll
        for (int half = 0; half < 2; half++)
            #pragma unroll
            for (int j = 0; j < 2; j++) {
                mma_bf16(oc[half * 2 + j], pah[kt2], bh[half][2 * j], bh[half][2 * j + 1]);
                mma_bf16(oc[half * 2 + j], pah[kt2], bl[half][2 * j], bl[half][2 * j + 1]);
                mma_bf16(oc[half * 2 + j], pal[kt2], bh[half][2 * j], bh[half][2 * j + 1]);
            }
    }

    // ---- store O as bf16 hi/lo ----
    #pragma unroll
    for (int rr = 0; rr < 2; rr++) {
        int l = r0 + rr * 8;
        int wi = l >> 3, wj = l & 7;
        int tk = (hy * 8 + wi) * 256 + (wx * 8 + wj);
        size_t obase = ((size_t)(b * T_TOT + tk)) * 128 + h * 32;
        #pragma unroll
        for (int ni = 0; ni < 4; ni++) {
            float v0 = rr ? oc[ni][2] : oc[ni][0];
            float v1 = rr ? oc[ni][3] : oc[ni][1];
            float h0 = __bfloat162float(__float2bfloat16(v0));
            float h1 = __bfloat162float(__float2bfloat16(v1));
            size_t off = obase + ni * 8 + t * 2;
            *(uint32_t*)(g_ctx_h + off) = pack_bf16x2(h0, h1);
            *(uint32_t*)(g_ctx_l + off) = pack_bf16x2(v0 - h0, v1 - h1);
        }
    }
}

// ---------------------------------------------------------------------------
// K3: det/inter token MHA.  Reads fp16 q/k, hi/lo v; writes hi/lo ctx.
// ---------------------------------------------------------------------------
__global__ __launch_bounds__(128)
void tok_attn_kernel()
{
    const int h  = blockIdx.x;
    const int bt = blockIdx.y;
    const int qc = blockIdx.z;
    const int b  = bt >> 1, ty = bt & 1;
    const int tbase = N_IMG + ty * TD_;
    const int tid = threadIdx.x, lane = tid & 31, warp = tid >> 5;

    __shared__ __align__(16) float kt[32][104];
    __shared__ __align__(16) float vs[100][32];
    __shared__ float ps[4][104];

    for (int idx = tid; idx < 100 * 4; idx += 128) {
        int tok = idx >> 2;
        int c8  = (idx & 3) * 8;
        size_t base = ((size_t)(b * T_TOT + tbase + tok)) * 128 + h * 32 + c8;
        uint4 kv = *(const uint4*)(g_k16 + base);
        const __half2* kp = (const __half2*)&kv;
        uint4 vhv = *(const uint4*)(g_v_h + base);
        uint4 vlv = *(const uint4*)(g_v_l + base);
        const __nv_bfloat162* hp = (const __nv_bfloat162*)&vhv;
        const __nv_bfloat162* lp = (const __nv_bfloat162*)&vlv;
        #pragma unroll
        for (int i = 0; i < 4; i++) {
            float2 kf = __half22float2(kp[i]);
            kt[c8 + 2 * i][tok]     = kf.x;
            kt[c8 + 2 * i + 1][tok] = kf.y;
            float2 hf = __bfloat1622float2(hp[i]);
            float2 lf = __bfloat1622float2(lp[i]);
            vs[tok][c8 + 2 * i]     = hf.x + lf.x;
            vs[tok][c8 + 2 * i + 1] = hf.y + lf.y;
        }
    }
    __syncthreads();

    const int q = qc * 4 + warp;
    float qv[32];
    {
        const __half* qp = g_q16 + ((size_t)(b * T_TOT + tbase + q)) * 128 + h * 32;
        #pragma unroll
        for (int d2 = 0; d2 < 16; d2++) {
            float2 f = __half22float2(*(const __half2*)(qp + d2 * 2));
            qv[d2 * 2]     = f.x * SCALE_;
            qv[d2 * 2 + 1] = f.y * SCALE_;
        }
    }
    float s[4];
    float mx = -1e30f;
    #pragma unroll
    for (int m = 0; m < 4; m++) {
        int j = lane + m * 32;
        float acc = -1e30f;
        if (j < 100) {
            acc = 0.f;
            #pragma unroll
            for (int d = 0; d < 32; d++) acc += qv[d] * kt[d][j];
        }
        s[m] = acc;
        mx = fmaxf(mx, acc);
    }
    #pragma unroll
    for (int o = 16; o > 0; o >>= 1)
        mx = fmaxf(mx, __shfl_xor_sync(0xffffffffu, mx, o));
    float sum = 0.f;
    #pragma unroll
    for (int m = 0; m < 4; m++) {
        int j = lane + m * 32;
        if (j < 100) { s[m] = __expf(s[m] - mx); sum += s[m]; }
        else s[m] = 0.f;
    }
    #pragma unroll
    for (int o = 16; o > 0; o >>= 1)
        sum += __shfl_xor_sync(0xffffffffu, sum, o);
    float inv = 1.0f / sum;
    #pragma unroll
    for (int m = 0; m < 4; m++) {
        int j = lane + m * 32;
        if (j < 100) ps[warp][j] = s[m] * inv;
    }
    __syncwarp();

    float o = 0.f;
    #pragma unroll 10
    for (int j = 0; j < 100; j++)
        o += ps[warp][j] * vs[j][lane];
    size_t off = ((size_t)(b * T_TOT + tbase + q)) * 128 + h * 32 + lane;
    __nv_bfloat16 hbf = __float2bfloat16(o);
    g_ctx_h[off] = hbf;
    g_ctx_l[off] = __float2bfloat16(o - __bfloat162float(hbf));
}

// ---------------------------------------------------------------------------
// kernel_launch
// ---------------------------------------------------------------------------
extern "C" void kernel_launch(void* const* d_in, const int* in_sizes, int n_in,
                              void* d_out, int out_size)
{
    (void)in_sizes; (void)n_in; (void)out_size;
    const float* x        = (const float*)d_in[0];
    const float* det      = (const float*)d_in[1];
    const float* inter    = (const float*)d_in[2];
    const float* mask     = (const float*)d_in[3];
    const float* W_qkv    = (const float*)d_in[4];
    const float* b_qkv    = (const float*)d_in[5];
    const float* W_proj   = (const float*)d_in[6];
    const float* b_proj   = (const float*)d_in[7];
    const float* rel_tab  = (const float*)d_in[8];
    const int*   rel_idx  = (const int*)d_in[9];
    float* out = (float*)d_out;

    const int m_tiles = (M_TOT + 127) / 128;   // 2055
    const int smem_bytes = 2 * 4 * 128 * 40 * 2;  // 81920

    cudaFuncSetAttribute(mma_gemm_kernel<true>,
                         cudaFuncAttributeMaxDynamicSharedMemorySize, smem_bytes);
    cudaFuncSetAttribute(mma_gemm_kernel<false>,
                         cudaFuncAttributeMaxDynamicSharedMemorySize, smem_bytes);

    bias_gather_kernel<<<16, 256>>>(rel_tab, rel_idx);
    weight_split_kernel<<<192, 256>>>(W_qkv, W_proj);
    mma_gemm_kernel<true><<<dim3(3, m_tiles), 256, smem_bytes>>>(x, det, inter,
                                                                 b_qkv, nullptr);
    win_attn_mma_kernel<<<dim3(NH_, NWIN, B_SZ), 128>>>(mask);
    tok_attn_kernel<<<dim3(NH_, B_SZ * 2, 25), 128>>>();
    mma_gemm_kernel<false><<<dim3(1, m_tiles), 256, smem_bytes>>>(nullptr, nullptr,
                                                                  nullptr, b_proj, out);
}